// round 15
// baseline (speedup 1.0000x reference)
#include <cuda_runtime.h>
#include <cuda_fp16.h>
#include <cstdint>
#include <math.h>

#define NTASK 64
#define NB    4096
#define TD    512
#define HD    256
#define VD    484
#define MT    64            // batch rows per CTA
#define THREADS 128

// ---- smem layout (bytes) ----
#define HSTR_B   272                             // h row stride (256 int8 + 16 pad)
#define SM_H     0
#define SM_H_SZ  (MT * HSTR_B)                   // 17408
#define STR_B    80                              // staged row stride (64 int8 + 16 pad)
#define SM_STAGE SM_H_SZ
#define A_BYTES  (MT * STR_B)                    // 5120
#define STAGE_BUF (A_BYTES + 256 * STR_B)        // 25600
#define SM_PARB  (SM_STAGE + 2 * STAGE_BUF)      // 68608
#define SMEM_TOTAL (SM_PARB + 2960 * 4)          // 80448

__device__ char  g_tfeat8[NB * TD];
__device__ char  g_w18[NTASK * HD * TD];
__device__ char  g_w28[NTASK * VD * HD];
__device__ float g_sa[NB];
__device__ float g_sw1[NTASK * HD];
__device__ float g_sw2[NTASK * VD];
__device__ unsigned int g_count;

__device__ __forceinline__ uint32_t s2u(const void* p) {
    uint32_t a;
    asm("{ .reg .u64 t; cvta.to.shared.u64 t, %1; cvt.u32.u64 %0, t; }" : "=r"(a) : "l"(p));
    return a;
}
__device__ __forceinline__ void cp16(uint32_t dst, const void* src) {
    asm volatile("cp.async.cg.shared.global [%0], [%1], 16;" :: "r"(dst), "l"(src) : "memory");
}
__device__ __forceinline__ void cpcommit() { asm volatile("cp.async.commit_group;" ::: "memory"); }
__device__ __forceinline__ void cpwait1()  { asm volatile("cp.async.wait_group 1;" ::: "memory"); }
__device__ __forceinline__ void cpwait0()  { asm volatile("cp.async.wait_group 0;" ::: "memory"); }

__device__ __forceinline__ void ldsm4(uint32_t* r, uint32_t a) {
    asm volatile("ldmatrix.sync.aligned.m8n8.x4.shared.b16 {%0,%1,%2,%3}, [%4];"
                 : "=r"(r[0]), "=r"(r[1]), "=r"(r[2]), "=r"(r[3]) : "r"(a));
}
// int8 MMA: m16n8k32, s32 accumulate (exact)
__device__ __forceinline__ void mma8i(int* c, const uint32_t* a, uint32_t b0, uint32_t b1) {
    asm volatile(
        "mma.sync.aligned.m16n8k32.row.col.s32.s8.s8.s32 "
        "{%0,%1,%2,%3}, {%4,%5,%6,%7}, {%8,%9}, {%0,%1,%2,%3};"
        : "+r"(c[0]), "+r"(c[1]), "+r"(c[2]), "+r"(c[3])
        : "r"(a[0]), "r"(a[1]), "r"(a[2]), "r"(a[3]), "r"(b0), "r"(b1));
}
__device__ __forceinline__ void sts16(uint32_t a, uint16_t v) {
    asm volatile("st.shared.u16 [%0], %1;" :: "r"(a), "h"(v) : "memory");
}
__device__ __forceinline__ void stz4(uint32_t a) {
    asm volatile("st.shared.v4.b32 [%0], {%1,%1,%1,%1};" :: "r"(a), "r"(0u) : "memory");
}
__device__ __forceinline__ int clamp127(int q) { return max(-127, min(127, q)); }
__device__ __forceinline__ uint32_t pack4(float a, float b, float c, float d, float inv) {
    const int qa = clamp127(__float2int_rn(a * inv));
    const int qb = clamp127(__float2int_rn(b * inv));
    const int qc = clamp127(__float2int_rn(c * inv));
    const int qd = clamp127(__float2int_rn(d * inv));
    return (uint32_t)(qa & 0xff) | ((uint32_t)(qb & 0xff) << 8) |
           ((uint32_t)(qc & 0xff) << 16) | ((uint32_t)(qd & 0xff) << 24);
}

// ---------------- convert + quantize kernel ----------------
__global__ void convert_kernel(const float* __restrict__ t_feat,
                               const float* __restrict__ W1,
                               const float* __restrict__ W2,
                               float* __restrict__ out, int out_size)
{
    const int lane = threadIdx.x & 31;
    const int gw = (blockIdx.x * blockDim.x + threadIdx.x) >> 5;
    const int nw = (gridDim.x * blockDim.x) >> 5;
    if (blockIdx.x == 0 && threadIdx.x < 65 && threadIdx.x < out_size) out[threadIdx.x] = 0.0f;

    const int R1 = NB;                 // 512-wide rows
    const int R2 = NTASK * HD;         // 512-wide rows
    const int R3 = NTASK * VD;         // 256-wide rows
    for (int w = gw; w < R1 + R2 + R3; w += nw) {
        if (w < R1 + R2) {
            const float* src = (w < R1) ? (t_feat + (size_t)w * TD)
                                        : (W1 + (size_t)(w - R1) * TD);
            float4 v[4];
#pragma unroll
            for (int i = 0; i < 4; ++i) v[i] = ((const float4*)src)[lane * 4 + i];
            float m = 0.f;
#pragma unroll
            for (int i = 0; i < 4; ++i)
                m = fmaxf(m, fmaxf(fmaxf(fabsf(v[i].x), fabsf(v[i].y)),
                                   fmaxf(fabsf(v[i].z), fabsf(v[i].w))));
#pragma unroll
            for (int o = 16; o > 0; o >>= 1) m = fmaxf(m, __shfl_xor_sync(~0u, m, o));
            m = fmaxf(m, 1e-20f);
            const float inv = 127.0f / m;
            uint4 p;
            p.x = pack4(v[0].x, v[0].y, v[0].z, v[0].w, inv);
            p.y = pack4(v[1].x, v[1].y, v[1].z, v[1].w, inv);
            p.z = pack4(v[2].x, v[2].y, v[2].z, v[2].w, inv);
            p.w = pack4(v[3].x, v[3].y, v[3].z, v[3].w, inv);
            char* dst = (w < R1) ? (g_tfeat8 + (size_t)w * TD)
                                 : (g_w18 + (size_t)(w - R1) * TD);
            ((uint4*)dst)[lane] = p;
            if (lane == 0) {
                if (w < R1) g_sa[w] = m * (1.0f / 127.0f);
                else        g_sw1[w - R1] = m * (1.0f / 127.0f);
            }
        } else {
            const int r = w - (R1 + R2);
            const float* src = W2 + (size_t)r * HD;
            float4 v[2];
#pragma unroll
            for (int i = 0; i < 2; ++i) v[i] = ((const float4*)src)[lane * 2 + i];
            float m = 0.f;
#pragma unroll
            for (int i = 0; i < 2; ++i)
                m = fmaxf(m, fmaxf(fmaxf(fabsf(v[i].x), fabsf(v[i].y)),
                                   fmaxf(fabsf(v[i].z), fabsf(v[i].w))));
#pragma unroll
            for (int o = 16; o > 0; o >>= 1) m = fmaxf(m, __shfl_xor_sync(~0u, m, o));
            m = fmaxf(m, 1e-20f);
            const float inv = 127.0f / m;
            uint2 p;
            p.x = pack4(v[0].x, v[0].y, v[0].z, v[0].w, inv);
            p.y = pack4(v[1].x, v[1].y, v[1].z, v[1].w, inv);
            ((uint2*)(g_w28 + (size_t)r * HD))[lane] = p;
            if (lane == 0) g_sw2[r] = m * (1.0f / 127.0f);
        }
    }
}

// ---------------- main fused kernel (4 warps, 64x64 tiles, 2 CTA/SM, int8) -----
__global__ void __launch_bounds__(THREADS, 2)
router_i8_kernel(const float* __restrict__ b1,
                 const float* __restrict__ gamma,
                 const float* __restrict__ beta,
                 const float* __restrict__ b2,
                 const float* __restrict__ cent,
                 float* __restrict__ out, int out_size)
{
    extern __shared__ char smem[];
    const uint32_t sb = s2u(smem);
    const int tid  = threadIdx.x;
    const int lane = tid & 31;
    const int wid  = tid >> 5;          // 0..3
    const int n0w  = wid * 64;
    const int task = blockIdx.y;
    const int brow0 = blockIdx.x * MT;

    const char* tA8  = g_tfeat8 + (size_t)brow0 * TD;
    const char* W1t8 = g_w18 + (size_t)task * HD * TD;
    const char* W2t8 = g_w28 + (size_t)task * VD * HD;

    float* b1s    = (float*)(smem + SM_PARB);
    float* gms    = b1s + 256;
    float* bts    = gms + 256;
    float* b2s    = bts + 256;     // 512
    float* cts    = b2s + 512;     // 512
    float* sw1s   = cts + 512;     // 256
    float* sw2s   = sw1s + 256;    // 512
    float* sas    = sw2s + 512;    // 64
    float* rowSum = sas + 64;      // 64
    float* rowSq  = rowSum + 64;   // 64
    float* vcA    = rowSq + 64;    // 64
    float* vvA    = vcA + 64;      // 64
    int*   hmaxI  = (int*)(vvA + 64);  // 64
    float* red    = (float*)(hmaxI + 64); // 8
    int*   flag   = (int*)(red + 8);

    const int arow   = lane & 15;
    const int acol16 = (lane >> 4) * 16;
    const int brow   = (lane & 7) | ((lane >> 4) << 3);
    const int bcol16 = ((lane >> 3) & 1) * 16;
    const uint32_t aOffW = (uint32_t)(arow * STR_B + acol16);
    const uint32_t bOffW = (uint32_t)((n0w + brow) * STR_B + bcol16);
    const uint32_t hOffW = (uint32_t)(arow * HSTR_B + acol16);

    // ---- prologue: issue GEMM1 chunk 0 (K=64 int8) ----
    {
        const uint32_t ab = sb + SM_STAGE;
        const uint32_t bb = ab + A_BYTES;
#pragma unroll
        for (int i = 0; i < 2; ++i) {
            const int s = tid + 128 * i, row = s >> 2, seg = s & 3;
            cp16(ab + (uint32_t)(row * STR_B + seg * 16), tA8 + (size_t)row * TD + seg * 16);
        }
#pragma unroll
        for (int i = 0; i < 8; ++i) {
            const int s = tid + 128 * i, row = s >> 2, seg = s & 3;
            cp16(bb + (uint32_t)(row * STR_B + seg * 16), W1t8 + (size_t)row * TD + seg * 16);
        }
        cpcommit();
    }

    // ---- params + zeros ----
#pragma unroll
    for (int i = 0; i < 2; ++i) {
        const int n = tid + 128 * i;
        b1s[n]  = b1[task * HD + n];
        gms[n]  = gamma[task * HD + n];
        bts[n]  = beta[task * HD + n];
        sw1s[n] = g_sw1[task * HD + n];
    }
    {
        float cc = 0.f;
#pragma unroll
        for (int i = 0; i < 4; ++i) {
            const int n = tid + 128 * i;
            float bv = 0.f, cv = 0.f, sv = 0.f;
            if (n < VD) {
                bv = b2[task * VD + n]; cv = cent[task * VD + n];
                sv = g_sw2[task * VD + n];
            }
            b2s[n] = bv; cts[n] = cv; sw2s[n] = sv;
            cc = fmaf(cv, cv, cc);
        }
#pragma unroll
        for (int o = 16; o > 0; o >>= 1) cc += __shfl_xor_sync(0xffffffffu, cc, o);
        if (lane == 0) red[wid] = cc;
    }
    if (tid < 64) {
        sas[tid] = g_sa[brow0 + tid];
        rowSum[tid] = 0.f; rowSq[tid] = 0.f; vcA[tid] = 0.f; vvA[tid] = 0.f;
        hmaxI[tid] = 0;
    }

    int acc[4][8][4];
#pragma unroll
    for (int mb = 0; mb < 4; ++mb)
#pragma unroll
        for (int q = 0; q < 8; ++q)
#pragma unroll
            for (int c = 0; c < 4; ++c) acc[mb][q][c] = 0;
    float (*accF)[8][4] = reinterpret_cast<float(*)[8][4]>(acc);

    // ================= GEMM1: K=512 = 8 chunks of K64, 2-stage ring ==============
    for (int c = 0; c < 8; ++c) {
        if (c < 7) {
            const int kb = (c + 1) * 64;
            const uint32_t ab = sb + SM_STAGE + (uint32_t)((c + 1) & 1) * STAGE_BUF;
            const uint32_t bb = ab + A_BYTES;
#pragma unroll
            for (int i = 0; i < 2; ++i) {
                const int s = tid + 128 * i, row = s >> 2, seg = s & 3;
                cp16(ab + (uint32_t)(row * STR_B + seg * 16),
                     tA8 + (size_t)row * TD + kb + seg * 16);
            }
#pragma unroll
            for (int i = 0; i < 8; ++i) {
                const int s = tid + 128 * i, row = s >> 2, seg = s & 3;
                cp16(bb + (uint32_t)(row * STR_B + seg * 16),
                     W1t8 + (size_t)row * TD + kb + seg * 16);
            }
            cpcommit();
            cpwait1();
        } else {
            cpwait0();
        }
        __syncthreads();
        const uint32_t ab = sb + SM_STAGE + (uint32_t)(c & 1) * STAGE_BUF;
        const uint32_t aA = ab + aOffW;
        const uint32_t bA = ab + A_BYTES + bOffW;

        uint32_t afr[2][4][4];
        uint32_t bfr[2][4];
#pragma unroll
        for (int mb = 0; mb < 4; ++mb) ldsm4(afr[0][mb], aA + (uint32_t)(mb * 16 * STR_B));
        ldsm4(bfr[0], bA);
#pragma unroll
        for (int ks = 0; ks < 2; ++ks)
#pragma unroll
            for (int q4 = 0; q4 < 4; ++q4) {
                const int s = ks * 4 + q4;
                if (ks == 0)
                    ldsm4(afr[1][q4], aA + (uint32_t)(q4 * 16 * STR_B + 32));
                if (s < 7) {
                    const int ns = s + 1, nks = ns >> 2, nq = ns & 3;
                    ldsm4(bfr[ns & 1], bA + (uint32_t)(nq * 16 * STR_B + nks * 32));
                }
                const uint32_t* bq = bfr[s & 1];
#pragma unroll
                for (int mb = 0; mb < 4; ++mb) {
                    mma8i(acc[mb][2 * q4],     afr[ks][mb], bq[0], bq[1]);
                    mma8i(acc[mb][2 * q4 + 1], afr[ks][mb], bq[2], bq[3]);
                }
            }
        __syncthreads();
    }

    // ---- issue GEMM2 chunk 0 (overlaps dequant/LN below) ----
    {
        const uint32_t bb = sb + SM_STAGE + A_BYTES;
#pragma unroll
        for (int i = 0; i < 8; ++i) {
            const int s = tid + 128 * i, row = s >> 2, seg = s & 3;
            const uint32_t dst = bb + (uint32_t)(row * STR_B + seg * 16);
            if (row < VD) cp16(dst, W2t8 + (size_t)row * HD + seg * 16);
            else          stz4(dst);
        }
        cpcommit();
    }

    // ================= dequant + LayerNorm stats =================
    {
        float sums[8], sqs[8];
#pragma unroll
        for (int k = 0; k < 8; ++k) { sums[k] = 0.f; sqs[k] = 0.f; }
#pragma unroll
        for (int mb = 0; mb < 4; ++mb) {
            const float sa0 = sas[mb * 16 + (lane >> 2)];
            const float sa1 = sas[mb * 16 + 8 + (lane >> 2)];
#pragma unroll
            for (int q = 0; q < 8; ++q)
#pragma unroll
                for (int c = 0; c < 4; ++c) {
                    const int n = n0w + q * 8 + 2 * (lane & 3) + (c & 1);
                    const float sa = (c >> 1) ? sa1 : sa0;
                    const float x = (float)acc[mb][q][c] * (sa * sw1s[n]) + b1s[n];
                    accF[mb][q][c] = x;
                    const int key = (mb << 1) | (c >> 1);
                    sums[key] += x;
                    sqs[key]  = fmaf(x, x, sqs[key]);
                }
        }
#pragma unroll
        for (int o = 1; o <= 2; o <<= 1)
#pragma unroll
            for (int k = 0; k < 8; ++k) {
                sums[k] += __shfl_xor_sync(0xffffffffu, sums[k], o);
                sqs[k]  += __shfl_xor_sync(0xffffffffu, sqs[k], o);
            }
        if ((lane & 3) == 0) {
#pragma unroll
            for (int k = 0; k < 8; ++k) {
                const int r = (k >> 1) * 16 + (k & 1) * 8 + (lane >> 2);
                atomicAdd(&rowSum[r], sums[k]);
                atomicAdd(&rowSq[r],  sqs[k]);
            }
        }
    }
    __syncthreads();

    // ================= normalize + GELU (keep in regs) + row max =================
#pragma unroll
    for (int mb = 0; mb < 4; ++mb)
#pragma unroll
        for (int cp = 0; cp < 2; ++cp) {
            const int r = mb * 16 + cp * 8 + (lane >> 2);
            const float mu   = rowSum[r] * (1.0f / HD);
            const float var  = rowSq[r] * (1.0f / HD) - mu * mu;
            const float rstd = rsqrtf(var + 1e-5f);
            float lmax = 0.f;
#pragma unroll
            for (int q = 0; q < 8; ++q)
#pragma unroll
                for (int cc = 0; cc < 2; ++cc) {
                    const int c = cp * 2 + cc;
                    const int n = n0w + q * 8 + 2 * (lane & 3) + cc;
                    float y = (accF[mb][q][c] - mu) * rstd * gms[n] + bts[n];
                    y = 0.5f * y * (1.0f + erff(y * 0.70710678118654752440f));
                    accF[mb][q][c] = y;
                    lmax = fmaxf(lmax, fabsf(y));
                }
            atomicMax(&hmaxI[r], __float_as_int(lmax));
        }
    __syncthreads();

    // ================= quantize h -> int8 smem =================
#pragma unroll
    for (int mb = 0; mb < 4; ++mb)
#pragma unroll
        for (int cp = 0; cp < 2; ++cp) {
            const int r = mb * 16 + cp * 8 + (lane >> 2);
            const float hm = __int_as_float(hmaxI[r]);
            const float inv = 127.0f / fmaxf(hm, 1e-20f);
#pragma unroll
            for (int q = 0; q < 8; ++q) {
                const int n = n0w + q * 8 + 2 * (lane & 3);
                const int q0 = clamp127(__float2int_rn(accF[mb][q][cp * 2]     * inv));
                const int q1 = clamp127(__float2int_rn(accF[mb][q][cp * 2 + 1] * inv));
                const uint16_t pk = (uint16_t)((q0 & 0xff) | ((q1 & 0xff) << 8));
                sts16(sb + SM_H + (uint32_t)(r * HSTR_B + n), pk);
            }
        }

    // zero accumulators for GEMM2
#pragma unroll
    for (int mb = 0; mb < 4; ++mb)
#pragma unroll
        for (int q = 0; q < 8; ++q)
#pragma unroll
            for (int c = 0; c < 4; ++c) acc[mb][q][c] = 0;

    // ================= GEMM2: 8 chunks (2 halves x K256=4) + cosine ==============
    float vc4[8], vv4[8];
#pragma unroll
    for (int k = 0; k < 8; ++k) { vc4[k] = 0.f; vv4[k] = 0.f; }

    for (int gc = 0; gc < 8; ++gc) {
        const int kc4 = gc & 3;
        if (gc == 4) {
            // fold half 0
#pragma unroll
            for (int mb = 0; mb < 4; ++mb) {
                const float sh0 = __int_as_float(hmaxI[mb * 16 + (lane >> 2)]) * (1.0f / 127.0f);
                const float sh1 = __int_as_float(hmaxI[mb * 16 + 8 + (lane >> 2)]) * (1.0f / 127.0f);
#pragma unroll
                for (int q = 0; q < 8; ++q)
#pragma unroll
                    for (int c = 0; c < 4; ++c) {
                        const int n = n0w + q * 8 + 2 * (lane & 3) + (c & 1);
                        const float sh = (c >> 1) ? sh1 : sh0;
                        const float v = (float)acc[mb][q][c] * (sh * sw2s[n]) + b2s[n];
                        const int key = (mb << 1) | (c >> 1);
                        vc4[key] = fmaf(v, cts[n], vc4[key]);
                        vv4[key] = fmaf(v, v,     vv4[key]);
                        acc[mb][q][c] = 0;
                    }
            }
        }
        if (gc < 7) {
            const int nh = (gc + 1) >> 2, nk = (gc + 1) & 3;
            const uint32_t bb = sb + SM_STAGE + (uint32_t)((gc + 1) & 1) * STAGE_BUF + A_BYTES;
            const int kb = nk * 64;
#pragma unroll
            for (int i = 0; i < 8; ++i) {
                const int s = tid + 128 * i, row = s >> 2, seg = s & 3;
                const int n = nh * 256 + row;
                const uint32_t dst = bb + (uint32_t)(row * STR_B + seg * 16);
                if (n < VD) cp16(dst, W2t8 + (size_t)n * HD + kb + seg * 16);
                else        stz4(dst);
            }
            cpcommit();
            cpwait1();
        } else {
            cpwait0();
        }
        __syncthreads();
        const uint32_t aA = sb + SM_H + hOffW + (uint32_t)(kc4 * 64);
        const uint32_t bA = sb + SM_STAGE + (uint32_t)(gc & 1) * STAGE_BUF + A_BYTES + bOffW;

        uint32_t afr[2][4][4];
        uint32_t bfr[2][4];
#pragma unroll
        for (int mb = 0; mb < 4; ++mb) ldsm4(afr[0][mb], aA + (uint32_t)(mb * 16 * HSTR_B));
        ldsm4(bfr[0], bA);
#pragma unroll
        for (int ks = 0; ks < 2; ++ks)
#pragma unroll
            for (int q4 = 0; q4 < 4; ++q4) {
                const int s = ks * 4 + q4;
                if (ks == 0)
                    ldsm4(afr[1][q4], aA + (uint32_t)(q4 * 16 * HSTR_B + 32));
                if (s < 7) {
                    const int ns = s + 1, nks = ns >> 2, nq = ns & 3;
                    ldsm4(bfr[ns & 1], bA + (uint32_t)(nq * 16 * STR_B + nks * 32));
                }
                const uint32_t* bq = bfr[s & 1];
#pragma unroll
                for (int mb = 0; mb < 4; ++mb) {
                    mma8i(acc[mb][2 * q4],     afr[ks][mb], bq[0], bq[1]);
                    mma8i(acc[mb][2 * q4 + 1], afr[ks][mb], bq[2], bq[3]);
                }
            }
        __syncthreads();
    }
    // fold half 1
#pragma unroll
    for (int mb = 0; mb < 4; ++mb) {
        const float sh0 = __int_as_float(hmaxI[mb * 16 + (lane >> 2)]) * (1.0f / 127.0f);
        const float sh1 = __int_as_float(hmaxI[mb * 16 + 8 + (lane >> 2)]) * (1.0f / 127.0f);
#pragma unroll
        for (int q = 0; q < 8; ++q)
#pragma unroll
            for (int c = 0; c < 4; ++c) {
                const int n = 256 + n0w + q * 8 + 2 * (lane & 3) + (c & 1);
                const float sh = (c >> 1) ? sh1 : sh0;
                const float v = (float)acc[mb][q][c] * (sh * sw2s[n]) + b2s[n];
                const int key = (mb << 1) | (c >> 1);
                vc4[key] = fmaf(v, cts[n], vc4[key]);
                vv4[key] = fmaf(v, v,     vv4[key]);
            }
    }

#pragma unroll
    for (int o = 1; o <= 2; o <<= 1)
#pragma unroll
        for (int k = 0; k < 8; ++k) {
            vc4[k] += __shfl_xor_sync(0xffffffffu, vc4[k], o);
            vv4[k] += __shfl_xor_sync(0xffffffffu, vv4[k], o);
        }
    if ((lane & 3) == 0) {
#pragma unroll
        for (int k = 0; k < 8; ++k) {
            const int r = (k >> 1) * 16 + (k & 1) * 8 + (lane >> 2);
            atomicAdd(&vcA[r], vc4[k]);
            atomicAdd(&vvA[r], vv4[k]);
        }
    }
    __syncthreads();

    float dist = 0.f;
    if (tid < 64) {
        float cn2 = red[0] + red[1] + red[2] + red[3];
        const float cn = fmaxf(sqrtf(cn2), 1e-8f);
        const float vn = fmaxf(sqrtf(vvA[tid]), 1e-8f);
        dist = 1.0f - vcA[tid] / (vn * cn);
    }
#pragma unroll
    for (int o = 16; o > 0; o >>= 1) dist += __shfl_xor_sync(0xffffffffu, dist, o);
    if (tid < 64 && lane == 0) red[4 + wid] = dist;
    __syncthreads();
    if (tid == 0) {
        if (task < out_size)
            atomicAdd(&out[task], red[4] + red[5]);
        __threadfence();
        const unsigned int old = atomicAdd(&g_count, 1u);
        *flag = (old == (unsigned)(NTASK * (NB / MT) - 1)) ? 1 : 0;
    }
    __syncthreads();

    // ---- last CTA finalizes: scale + argmin ----
    if (*flag) {
        __threadfence();
        float v = 0.0f;
        if (tid < NTASK && tid < out_size) {
            v = out[tid] * (1.0f / (float)NB);
            out[tid] = v;
        }
        if (tid < NTASK) b1s[tid] = v;
        __syncthreads();
        if (tid == 0) {
            int best = 0;
            float bv = b1s[0];
#pragma unroll 1
            for (int i = 1; i < NTASK; ++i)
                if (b1s[i] < bv) { bv = b1s[i]; best = i; }
            if (out_size > 64) out[64] = (float)best;
            g_count = 0u;
        }
    }
}

extern "C" void kernel_launch(void* const* d_in, const int* in_sizes, int n_in,
                              void* d_out, int out_size) {
    const float* t_feat = (const float*)d_in[0];
    const float* W1     = (const float*)d_in[1];
    const float* b1     = (const float*)d_in[2];
    const float* gamma  = (const float*)d_in[3];
    const float* beta   = (const float*)d_in[4];
    const float* W2     = (const float*)d_in[5];
    const float* b2     = (const float*)d_in[6];
    const float* cent   = (const float*)d_in[7];
    float* out = (float*)d_out;

    cudaFuncSetAttribute(router_i8_kernel,
                         cudaFuncAttributeMaxDynamicSharedMemorySize, SMEM_TOTAL);

    convert_kernel<<<2048, 256>>>(t_feat, W1, W2, out, out_size);
    dim3 grid(NB / MT, NTASK);
    router_i8_kernel<<<grid, THREADS, SMEM_TOTAL>>>(
        b1, gamma, beta, b2, cent, out, out_size);
}

// round 16
// speedup vs baseline: 1.8755x; 1.8755x over previous
#include <cuda_runtime.h>
#include <cuda_fp16.h>
#include <cstdint>
#include <math.h>

#define NTASK 64
#define NB    4096
#define TD    512
#define HD    256
#define VD    484
#define MT    64            // batch rows per CTA
#define THREADS 128

// ---- smem layout (bytes) ----
#define HSTR_B   272                             // h row stride (256 fp8 + 16 pad)
#define SM_H     0
#define SM_H_SZ  (MT * HSTR_B)                   // 17408
#define STR_B    80                              // staged row stride (64 fp8 + 16 pad)
#define SM_STAGE SM_H_SZ
#define A_BYTES  (MT * STR_B)                    // 5120
#define STAGE_BUF (A_BYTES + 256 * STR_B)        // 25600
#define SM_PARB  (SM_STAGE + 2 * STAGE_BUF)      // 68608
#define SMEM_TOTAL (SM_PARB + 2960 * 4)          // 80448

__device__ char  g_tfeat8[NB * TD];
__device__ char  g_w18[NTASK * HD * TD];
__device__ char  g_w28[NTASK * VD * HD];
__device__ float g_sa[NB];
__device__ float g_sw1[NTASK * HD];
__device__ float g_sw2[NTASK * VD];
__device__ unsigned int g_count;

__device__ __forceinline__ uint32_t s2u(const void* p) {
    uint32_t a;
    asm("{ .reg .u64 t; cvta.to.shared.u64 t, %1; cvt.u32.u64 %0, t; }" : "=r"(a) : "l"(p));
    return a;
}
__device__ __forceinline__ void cp16(uint32_t dst, const void* src) {
    asm volatile("cp.async.cg.shared.global [%0], [%1], 16;" :: "r"(dst), "l"(src) : "memory");
}
__device__ __forceinline__ void cpcommit() { asm volatile("cp.async.commit_group;" ::: "memory"); }
__device__ __forceinline__ void cpwait1()  { asm volatile("cp.async.wait_group 1;" ::: "memory"); }
__device__ __forceinline__ void cpwait0()  { asm volatile("cp.async.wait_group 0;" ::: "memory"); }

__device__ __forceinline__ void ldsm4(uint32_t* r, uint32_t a) {
    asm volatile("ldmatrix.sync.aligned.m8n8.x4.shared.b16 {%0,%1,%2,%3}, [%4];"
                 : "=r"(r[0]), "=r"(r[1]), "=r"(r[2]), "=r"(r[3]) : "r"(a));
}
// fp8 e4m3 MMA: m16n8k32, f32 accumulate
__device__ __forceinline__ void mma8f(float* c, const uint32_t* a, uint32_t b0, uint32_t b1) {
    asm volatile(
        "mma.sync.aligned.m16n8k32.row.col.f32.e4m3.e4m3.f32 "
        "{%0,%1,%2,%3}, {%4,%5,%6,%7}, {%8,%9}, {%0,%1,%2,%3};"
        : "+f"(c[0]), "+f"(c[1]), "+f"(c[2]), "+f"(c[3])
        : "r"(a[0]), "r"(a[1]), "r"(a[2]), "r"(a[3]), "r"(b0), "r"(b1));
}
__device__ __forceinline__ void sts16(uint32_t a, uint16_t v) {
    asm volatile("st.shared.u16 [%0], %1;" :: "r"(a), "h"(v) : "memory");
}
__device__ __forceinline__ void stz4(uint32_t a) {
    asm volatile("st.shared.v4.b32 [%0], {%1,%1,%1,%1};" :: "r"(a), "r"(0u) : "memory");
}
// pack two floats into e4m3x2 (hi in byte1, lo in byte0)
__device__ __forceinline__ uint16_t pk_e4m3x2(float hi, float lo) {
    uint16_t r;
    asm("cvt.rn.satfinite.e4m3x2.f32 %0, %1, %2;" : "=h"(r) : "f"(hi), "f"(lo));
    return r;
}
__device__ __forceinline__ uint32_t pack4_e4m3(float a, float b, float c, float d, float inv) {
    const uint32_t lo = pk_e4m3x2(b * inv, a * inv);
    const uint32_t hi = pk_e4m3x2(d * inv, c * inv);
    return lo | (hi << 16);
}

// ---------------- convert + quantize kernel (per-row e4m3, max -> 256) --------
__global__ void convert_kernel(const float* __restrict__ t_feat,
                               const float* __restrict__ W1,
                               const float* __restrict__ W2,
                               float* __restrict__ out, int out_size)
{
    const int lane = threadIdx.x & 31;
    const int gw = (blockIdx.x * blockDim.x + threadIdx.x) >> 5;
    const int nw = (gridDim.x * blockDim.x) >> 5;
    if (blockIdx.x == 0 && threadIdx.x < 65 && threadIdx.x < out_size) out[threadIdx.x] = 0.0f;

    const int R1 = NB;                 // 512-wide rows
    const int R2 = NTASK * HD;         // 512-wide rows
    const int R3 = NTASK * VD;         // 256-wide rows
    for (int w = gw; w < R1 + R2 + R3; w += nw) {
        if (w < R1 + R2) {
            const float* src = (w < R1) ? (t_feat + (size_t)w * TD)
                                        : (W1 + (size_t)(w - R1) * TD);
            float4 v[4];
#pragma unroll
            for (int i = 0; i < 4; ++i) v[i] = ((const float4*)src)[lane * 4 + i];
            float m = 0.f;
#pragma unroll
            for (int i = 0; i < 4; ++i)
                m = fmaxf(m, fmaxf(fmaxf(fabsf(v[i].x), fabsf(v[i].y)),
                                   fmaxf(fabsf(v[i].z), fabsf(v[i].w))));
#pragma unroll
            for (int o = 16; o > 0; o >>= 1) m = fmaxf(m, __shfl_xor_sync(~0u, m, o));
            m = fmaxf(m, 1e-20f);
            const float inv = 256.0f / m;
            uint4 p;
            p.x = pack4_e4m3(v[0].x, v[0].y, v[0].z, v[0].w, inv);
            p.y = pack4_e4m3(v[1].x, v[1].y, v[1].z, v[1].w, inv);
            p.z = pack4_e4m3(v[2].x, v[2].y, v[2].z, v[2].w, inv);
            p.w = pack4_e4m3(v[3].x, v[3].y, v[3].z, v[3].w, inv);
            char* dst = (w < R1) ? (g_tfeat8 + (size_t)w * TD)
                                 : (g_w18 + (size_t)(w - R1) * TD);
            ((uint4*)dst)[lane] = p;
            if (lane == 0) {
                if (w < R1) g_sa[w] = m * (1.0f / 256.0f);
                else        g_sw1[w - R1] = m * (1.0f / 256.0f);
            }
        } else {
            const int r = w - (R1 + R2);
            const float* src = W2 + (size_t)r * HD;
            float4 v[2];
#pragma unroll
            for (int i = 0; i < 2; ++i) v[i] = ((const float4*)src)[lane * 2 + i];
            float m = 0.f;
#pragma unroll
            for (int i = 0; i < 2; ++i)
                m = fmaxf(m, fmaxf(fmaxf(fabsf(v[i].x), fabsf(v[i].y)),
                                   fmaxf(fabsf(v[i].z), fabsf(v[i].w))));
#pragma unroll
            for (int o = 16; o > 0; o >>= 1) m = fmaxf(m, __shfl_xor_sync(~0u, m, o));
            m = fmaxf(m, 1e-20f);
            const float inv = 256.0f / m;
            uint2 p;
            p.x = pack4_e4m3(v[0].x, v[0].y, v[0].z, v[0].w, inv);
            p.y = pack4_e4m3(v[1].x, v[1].y, v[1].z, v[1].w, inv);
            ((uint2*)(g_w28 + (size_t)r * HD))[lane] = p;
            if (lane == 0) g_sw2[r] = m * (1.0f / 256.0f);
        }
    }
}

// ---------------- main fused kernel (4 warps, 64x64 tiles, 2 CTA/SM, fp8) ------
__global__ void __launch_bounds__(THREADS, 2)
router_f8_kernel(const float* __restrict__ b1,
                 const float* __restrict__ gamma,
                 const float* __restrict__ beta,
                 const float* __restrict__ b2,
                 const float* __restrict__ cent,
                 float* __restrict__ out, int out_size)
{
    extern __shared__ char smem[];
    const uint32_t sb = s2u(smem);
    const int tid  = threadIdx.x;
    const int lane = tid & 31;
    const int wid  = tid >> 5;          // 0..3
    const int n0w  = wid * 64;
    const int task = blockIdx.y;
    const int brow0 = blockIdx.x * MT;

    const char* tA8  = g_tfeat8 + (size_t)brow0 * TD;
    const char* W1t8 = g_w18 + (size_t)task * HD * TD;
    const char* W2t8 = g_w28 + (size_t)task * VD * HD;

    float* b1s    = (float*)(smem + SM_PARB);
    float* gms    = b1s + 256;
    float* bts    = gms + 256;
    float* b2s    = bts + 256;     // 512
    float* cts    = b2s + 512;     // 512
    float* sw1s   = cts + 512;     // 256
    float* sw2s   = sw1s + 256;    // 512
    float* sas    = sw2s + 512;    // 64
    float* rowSum = sas + 64;      // 64
    float* rowSq  = rowSum + 64;   // 64
    float* vcA    = rowSq + 64;    // 64
    float* vvA    = vcA + 64;      // 64
    int*   hmaxI  = (int*)(vvA + 64);  // 64
    float* red    = (float*)(hmaxI + 64); // 8
    int*   flag   = (int*)(red + 8);

    const int arow   = lane & 15;
    const int acol16 = (lane >> 4) * 16;
    const int brow   = (lane & 7) | ((lane >> 4) << 3);
    const int bcol16 = ((lane >> 3) & 1) * 16;
    const uint32_t aOffW = (uint32_t)(arow * STR_B + acol16);
    const uint32_t bOffW = (uint32_t)((n0w + brow) * STR_B + bcol16);
    const uint32_t hOffW = (uint32_t)(arow * HSTR_B + acol16);

    // ---- prologue: issue GEMM1 chunk 0 (K=64 fp8) ----
    {
        const uint32_t ab = sb + SM_STAGE;
        const uint32_t bb = ab + A_BYTES;
#pragma unroll
        for (int i = 0; i < 2; ++i) {
            const int s = tid + 128 * i, row = s >> 2, seg = s & 3;
            cp16(ab + (uint32_t)(row * STR_B + seg * 16), tA8 + (size_t)row * TD + seg * 16);
        }
#pragma unroll
        for (int i = 0; i < 8; ++i) {
            const int s = tid + 128 * i, row = s >> 2, seg = s & 3;
            cp16(bb + (uint32_t)(row * STR_B + seg * 16), W1t8 + (size_t)row * TD + seg * 16);
        }
        cpcommit();
    }

    // ---- params + zeros ----
#pragma unroll
    for (int i = 0; i < 2; ++i) {
        const int n = tid + 128 * i;
        b1s[n]  = b1[task * HD + n];
        gms[n]  = gamma[task * HD + n];
        bts[n]  = beta[task * HD + n];
        sw1s[n] = g_sw1[task * HD + n];
    }
    {
        float cc = 0.f;
#pragma unroll
        for (int i = 0; i < 4; ++i) {
            const int n = tid + 128 * i;
            float bv = 0.f, cv = 0.f, sv = 0.f;
            if (n < VD) {
                bv = b2[task * VD + n]; cv = cent[task * VD + n];
                sv = g_sw2[task * VD + n];
            }
            b2s[n] = bv; cts[n] = cv; sw2s[n] = sv;
            cc = fmaf(cv, cv, cc);
        }
#pragma unroll
        for (int o = 16; o > 0; o >>= 1) cc += __shfl_xor_sync(0xffffffffu, cc, o);
        if (lane == 0) red[wid] = cc;
    }
    if (tid < 64) {
        sas[tid] = g_sa[brow0 + tid];
        rowSum[tid] = 0.f; rowSq[tid] = 0.f; vcA[tid] = 0.f; vvA[tid] = 0.f;
        hmaxI[tid] = 0;
    }

    float acc[4][8][4];
#pragma unroll
    for (int mb = 0; mb < 4; ++mb)
#pragma unroll
        for (int q = 0; q < 8; ++q)
#pragma unroll
            for (int c = 0; c < 4; ++c) acc[mb][q][c] = 0.f;

    // ================= GEMM1: K=512 = 8 chunks of K64, 2-stage ring ==============
    for (int c = 0; c < 8; ++c) {
        if (c < 7) {
            const int kb = (c + 1) * 64;
            const uint32_t ab = sb + SM_STAGE + (uint32_t)((c + 1) & 1) * STAGE_BUF;
            const uint32_t bb = ab + A_BYTES;
#pragma unroll
            for (int i = 0; i < 2; ++i) {
                const int s = tid + 128 * i, row = s >> 2, seg = s & 3;
                cp16(ab + (uint32_t)(row * STR_B + seg * 16),
                     tA8 + (size_t)row * TD + kb + seg * 16);
            }
#pragma unroll
            for (int i = 0; i < 8; ++i) {
                const int s = tid + 128 * i, row = s >> 2, seg = s & 3;
                cp16(bb + (uint32_t)(row * STR_B + seg * 16),
                     W1t8 + (size_t)row * TD + kb + seg * 16);
            }
            cpcommit();
            cpwait1();
        } else {
            cpwait0();
        }
        __syncthreads();
        const uint32_t ab = sb + SM_STAGE + (uint32_t)(c & 1) * STAGE_BUF;
        const uint32_t aA = ab + aOffW;
        const uint32_t bA = ab + A_BYTES + bOffW;

        uint32_t afr[2][4][4];
        uint32_t bfr[2][4];
#pragma unroll
        for (int mb = 0; mb < 4; ++mb) ldsm4(afr[0][mb], aA + (uint32_t)(mb * 16 * STR_B));
        ldsm4(bfr[0], bA);
#pragma unroll
        for (int ks = 0; ks < 2; ++ks)
#pragma unroll
            for (int q4 = 0; q4 < 4; ++q4) {
                const int s = ks * 4 + q4;
                if (ks == 0)
                    ldsm4(afr[1][q4], aA + (uint32_t)(q4 * 16 * STR_B + 32));
                if (s < 7) {
                    const int ns = s + 1, nks = ns >> 2, nq = ns & 3;
                    ldsm4(bfr[ns & 1], bA + (uint32_t)(nq * 16 * STR_B + nks * 32));
                }
                const uint32_t* bq = bfr[s & 1];
#pragma unroll
                for (int mb = 0; mb < 4; ++mb) {
                    mma8f(acc[mb][2 * q4],     afr[ks][mb], bq[0], bq[1]);
                    mma8f(acc[mb][2 * q4 + 1], afr[ks][mb], bq[2], bq[3]);
                }
            }
        __syncthreads();
    }

    // ---- issue GEMM2 chunk 0 (overlaps dequant/LN below) ----
    {
        const uint32_t bb = sb + SM_STAGE + A_BYTES;
#pragma unroll
        for (int i = 0; i < 8; ++i) {
            const int s = tid + 128 * i, row = s >> 2, seg = s & 3;
            const uint32_t dst = bb + (uint32_t)(row * STR_B + seg * 16);
            if (row < VD) cp16(dst, W2t8 + (size_t)row * HD + seg * 16);
            else          stz4(dst);
        }
        cpcommit();
    }

    // ================= dequant + LayerNorm stats =================
    {
        float sums[8], sqs[8];
#pragma unroll
        for (int k = 0; k < 8; ++k) { sums[k] = 0.f; sqs[k] = 0.f; }
#pragma unroll
        for (int mb = 0; mb < 4; ++mb) {
            const float sa0 = sas[mb * 16 + (lane >> 2)];
            const float sa1 = sas[mb * 16 + 8 + (lane >> 2)];
#pragma unroll
            for (int q = 0; q < 8; ++q)
#pragma unroll
                for (int c = 0; c < 4; ++c) {
                    const int n = n0w + q * 8 + 2 * (lane & 3) + (c & 1);
                    const float sa = (c >> 1) ? sa1 : sa0;
                    const float x = acc[mb][q][c] * (sa * sw1s[n]) + b1s[n];
                    acc[mb][q][c] = x;
                    const int key = (mb << 1) | (c >> 1);
                    sums[key] += x;
                    sqs[key]  = fmaf(x, x, sqs[key]);
                }
        }
#pragma unroll
        for (int o = 1; o <= 2; o <<= 1)
#pragma unroll
            for (int k = 0; k < 8; ++k) {
                sums[k] += __shfl_xor_sync(0xffffffffu, sums[k], o);
                sqs[k]  += __shfl_xor_sync(0xffffffffu, sqs[k], o);
            }
        if ((lane & 3) == 0) {
#pragma unroll
            for (int k = 0; k < 8; ++k) {
                const int r = (k >> 1) * 16 + (k & 1) * 8 + (lane >> 2);
                atomicAdd(&rowSum[r], sums[k]);
                atomicAdd(&rowSq[r],  sqs[k]);
            }
        }
    }
    __syncthreads();

    // ================= normalize + GELU (keep in regs) + row max =================
#pragma unroll
    for (int mb = 0; mb < 4; ++mb)
#pragma unroll
        for (int cp = 0; cp < 2; ++cp) {
            const int r = mb * 16 + cp * 8 + (lane >> 2);
            const float mu   = rowSum[r] * (1.0f / HD);
            const float var  = rowSq[r] * (1.0f / HD) - mu * mu;
            const float rstd = rsqrtf(var + 1e-5f);
            float lmax = 0.f;
#pragma unroll
            for (int q = 0; q < 8; ++q)
#pragma unroll
                for (int cc = 0; cc < 2; ++cc) {
                    const int c = cp * 2 + cc;
                    const int n = n0w + q * 8 + 2 * (lane & 3) + cc;
                    float y = (acc[mb][q][c] - mu) * rstd * gms[n] + bts[n];
                    y = 0.5f * y * (1.0f + erff(y * 0.70710678118654752440f));
                    acc[mb][q][c] = y;
                    lmax = fmaxf(lmax, fabsf(y));
                }
            atomicMax(&hmaxI[r], __float_as_int(lmax));
        }
    __syncthreads();

    // ================= quantize h -> e4m3 smem =================
#pragma unroll
    for (int mb = 0; mb < 4; ++mb)
#pragma unroll
        for (int cp = 0; cp < 2; ++cp) {
            const int r = mb * 16 + cp * 8 + (lane >> 2);
            const float hm = __int_as_float(hmaxI[r]);
            const float inv = 256.0f / fmaxf(hm, 1e-20f);
#pragma unroll
            for (int q = 0; q < 8; ++q) {
                const int n = n0w + q * 8 + 2 * (lane & 3);
                const uint16_t pk = pk_e4m3x2(acc[mb][q][cp * 2 + 1] * inv,
                                              acc[mb][q][cp * 2]     * inv);
                sts16(sb + SM_H + (uint32_t)(r * HSTR_B + n), pk);
            }
        }

    // zero accumulators for GEMM2
#pragma unroll
    for (int mb = 0; mb < 4; ++mb)
#pragma unroll
        for (int q = 0; q < 8; ++q)
#pragma unroll
            for (int c = 0; c < 4; ++c) acc[mb][q][c] = 0.f;

    // ================= GEMM2: 8 chunks (2 halves x K256=4) + cosine ==============
    float vc4[8], vv4[8];
#pragma unroll
    for (int k = 0; k < 8; ++k) { vc4[k] = 0.f; vv4[k] = 0.f; }

    for (int gc = 0; gc < 8; ++gc) {
        const int kc4 = gc & 3;
        if (gc == 4) {
            // fold half 0
#pragma unroll
            for (int mb = 0; mb < 4; ++mb) {
                const float sh0 = __int_as_float(hmaxI[mb * 16 + (lane >> 2)]) * (1.0f / 256.0f);
                const float sh1 = __int_as_float(hmaxI[mb * 16 + 8 + (lane >> 2)]) * (1.0f / 256.0f);
#pragma unroll
                for (int q = 0; q < 8; ++q)
#pragma unroll
                    for (int c = 0; c < 4; ++c) {
                        const int n = n0w + q * 8 + 2 * (lane & 3) + (c & 1);
                        const float sh = (c >> 1) ? sh1 : sh0;
                        const float v = acc[mb][q][c] * (sh * sw2s[n]) + b2s[n];
                        const int key = (mb << 1) | (c >> 1);
                        vc4[key] = fmaf(v, cts[n], vc4[key]);
                        vv4[key] = fmaf(v, v,     vv4[key]);
                        acc[mb][q][c] = 0.f;
                    }
            }
        }
        if (gc < 7) {
            const int nh = (gc + 1) >> 2, nk = (gc + 1) & 3;
            const uint32_t bb = sb + SM_STAGE + (uint32_t)((gc + 1) & 1) * STAGE_BUF + A_BYTES;
            const int kb = nk * 64;
#pragma unroll
            for (int i = 0; i < 8; ++i) {
                const int s = tid + 128 * i, row = s >> 2, seg = s & 3;
                const int n = nh * 256 + row;
                const uint32_t dst = bb + (uint32_t)(row * STR_B + seg * 16);
                if (n < VD) cp16(dst, W2t8 + (size_t)n * HD + kb + seg * 16);
                else        stz4(dst);
            }
            cpcommit();
            cpwait1();
        } else {
            cpwait0();
        }
        __syncthreads();
        const uint32_t aA = sb + SM_H + hOffW + (uint32_t)(kc4 * 64);
        const uint32_t bA = sb + SM_STAGE + (uint32_t)(gc & 1) * STAGE_BUF + A_BYTES + bOffW;

        uint32_t afr[2][4][4];
        uint32_t bfr[2][4];
#pragma unroll
        for (int mb = 0; mb < 4; ++mb) ldsm4(afr[0][mb], aA + (uint32_t)(mb * 16 * HSTR_B));
        ldsm4(bfr[0], bA);
#pragma unroll
        for (int ks = 0; ks < 2; ++ks)
#pragma unroll
            for (int q4 = 0; q4 < 4; ++q4) {
                const int s = ks * 4 + q4;
                if (ks == 0)
                    ldsm4(afr[1][q4], aA + (uint32_t)(q4 * 16 * HSTR_B + 32));
                if (s < 7) {
                    const int ns = s + 1, nks = ns >> 2, nq = ns & 3;
                    ldsm4(bfr[ns & 1], bA + (uint32_t)(nq * 16 * STR_B + nks * 32));
                }
                const uint32_t* bq = bfr[s & 1];
#pragma unroll
                for (int mb = 0; mb < 4; ++mb) {
                    mma8f(acc[mb][2 * q4],     afr[ks][mb], bq[0], bq[1]);
                    mma8f(acc[mb][2 * q4 + 1], afr[ks][mb], bq[2], bq[3]);
                }
            }
        __syncthreads();
    }
    // fold half 1
#pragma unroll
    for (int mb = 0; mb < 4; ++mb) {
        const float sh0 = __int_as_float(hmaxI[mb * 16 + (lane >> 2)]) * (1.0f / 256.0f);
        const float sh1 = __int_as_float(hmaxI[mb * 16 + 8 + (lane >> 2)]) * (1.0f / 256.0f);
#pragma unroll
        for (int q = 0; q < 8; ++q)
#pragma unroll
            for (int c = 0; c < 4; ++c) {
                const int n = 256 + n0w + q * 8 + 2 * (lane & 3) + (c & 1);
                const float sh = (c >> 1) ? sh1 : sh0;
                const float v = acc[mb][q][c] * (sh * sw2s[n]) + b2s[n];
                const int key = (mb << 1) | (c >> 1);
                vc4[key] = fmaf(v, cts[n], vc4[key]);
                vv4[key] = fmaf(v, v,     vv4[key]);
            }
    }

#pragma unroll
    for (int o = 1; o <= 2; o <<= 1)
#pragma unroll
        for (int k = 0; k < 8; ++k) {
            vc4[k] += __shfl_xor_sync(0xffffffffu, vc4[k], o);
            vv4[k] += __shfl_xor_sync(0xffffffffu, vv4[k], o);
        }
    if ((lane & 3) == 0) {
#pragma unroll
        for (int k = 0; k < 8; ++k) {
            const int r = (k >> 1) * 16 + (k & 1) * 8 + (lane >> 2);
            atomicAdd(&vcA[r], vc4[k]);
            atomicAdd(&vvA[r], vv4[k]);
        }
    }
    __syncthreads();

    float dist = 0.f;
    if (tid < 64) {
        float cn2 = red[0] + red[1] + red[2] + red[3];
        const float cn = fmaxf(sqrtf(cn2), 1e-8f);
        const float vn = fmaxf(sqrtf(vvA[tid]), 1e-8f);
        dist = 1.0f - vcA[tid] / (vn * cn);
    }
#pragma unroll
    for (int o = 16; o > 0; o >>= 1) dist += __shfl_xor_sync(0xffffffffu, dist, o);
    if (tid < 64 && lane == 0) red[4 + wid] = dist;
    __syncthreads();
    if (tid == 0) {
        if (task < out_size)
            atomicAdd(&out[task], red[4] + red[5]);
        __threadfence();
        const unsigned int old = atomicAdd(&g_count, 1u);
        *flag = (old == (unsigned)(NTASK * (NB / MT) - 1)) ? 1 : 0;
    }
    __syncthreads();

    // ---- last CTA finalizes: scale + argmin ----
    if (*flag) {
        __threadfence();
        float v = 0.0f;
        if (tid < NTASK && tid < out_size) {
            v = out[tid] * (1.0f / (float)NB);
            out[tid] = v;
        }
        if (tid < NTASK) b1s[tid] = v;
        __syncthreads();
        if (tid == 0) {
            int best = 0;
            float bv = b1s[0];
#pragma unroll 1
            for (int i = 1; i < NTASK; ++i)
                if (b1s[i] < bv) { bv = b1s[i]; best = i; }
            if (out_size > 64) out[64] = (float)best;
            g_count = 0u;
        }
    }
}

extern "C" void kernel_launch(void* const* d_in, const int* in_sizes, int n_in,
                              void* d_out, int out_size) {
    const float* t_feat = (const float*)d_in[0];
    const float* W1     = (const float*)d_in[1];
    const float* b1     = (const float*)d_in[2];
    const float* gamma  = (const float*)d_in[3];
    const float* beta   = (const float*)d_in[4];
    const float* W2     = (const float*)d_in[5];
    const float* b2     = (const float*)d_in[6];
    const float* cent   = (const float*)d_in[7];
    float* out = (float*)d_out;

    cudaFuncSetAttribute(router_f8_kernel,
                         cudaFuncAttributeMaxDynamicSharedMemorySize, SMEM_TOTAL);

    convert_kernel<<<2048, 256>>>(t_feat, W1, W2, out, out_size);
    dim3 grid(NB / MT, NTASK);
    router_f8_kernel<<<grid, THREADS, SMEM_TOTAL>>>(
        b1, gamma, beta, b2, cent, out, out_size);
}